// round 9
// baseline (speedup 1.0000x reference)
#include <cuda_runtime.h>
#include <cstdint>

#define BSZ    256
#define BOND   5
#define NDIM   128
#define ATOM   64
#define UNITS  128
#define THREADS 256

// smem float-word pitches (conflict-free fragment access; pitch % 32 == 4 or 8)
#define P_F    72    // F   [n=128][d=64]   (pre-rounded tf32 at staging)
#define P_ADJ  132   // adj [m=128][n=128]
#define P_K    136   // K   [d=64][u=128]
#define P_X1   68    // X1  [m=128][d=64]   (single buffer)

// smem layout in float words: F | adj | K0 | K1 | X1
#define OFF_F    0
#define OFF_ADJ  (OFF_F   + NDIM * P_F)     // 9216
#define OFF_K0   (OFF_ADJ + NDIM * P_ADJ)   // 26112
#define OFF_K1   (OFF_K0  + ATOM * P_K)     // 34816
#define OFF_X1   (OFF_K1  + ATOM * P_K)     // 43520
#define SMEM_WORDS (OFF_X1 + NDIM * P_X1)   // 52224
#define SMEM_BYTES (SMEM_WORDS * 4)         // 208896 (< 227KB)

__device__ __forceinline__ float f2tf32f(float f) {
    uint32_t u;
    asm("cvt.rna.tf32.f32 %0, %1;" : "=r"(u) : "f"(f));
    return __uint_as_float(u);
}

__device__ __forceinline__ void mma_tf32(float c[4], const uint32_t a[4], const uint32_t b[2]) {
    asm volatile(
        "mma.sync.aligned.m16n8k8.row.col.f32.tf32.tf32.f32 "
        "{%0,%1,%2,%3}, {%4,%5,%6,%7}, {%8,%9}, {%0,%1,%2,%3};"
        : "+f"(c[0]), "+f"(c[1]), "+f"(c[2]), "+f"(c[3])
        : "r"(a[0]), "r"(a[1]), "r"(a[2]), "r"(a[3]), "r"(b[0]), "r"(b[1]));
}

__device__ __forceinline__ uint32_t smem_u32(const void* p) {
    uint32_t a;
    asm("{ .reg .u64 t; cvta.to.shared.u64 t, %1; cvt.u32.u64 %0, t; }" : "=r"(a) : "l"(p));
    return a;
}
__device__ __forceinline__ void cpa16(uint32_t s, const float4* g) {
    asm volatile("cp.async.cg.shared.global [%0], [%1], 16;" :: "r"(s), "l"(g) : "memory");
}
#define CP_COMMIT() asm volatile("cp.async.commit_group;" ::: "memory")
template<int N> __device__ __forceinline__ void cp_wait() {
    asm volatile("cp.async.wait_group %0;" :: "n"(N) : "memory");
}

__global__ void __launch_bounds__(THREADS, 1)
rgc_kernel(const float* __restrict__ adjacency,
           const float* __restrict__ features,
           const float* __restrict__ kern,
           float* __restrict__ out) {
    extern __shared__ float sm[];
    float* sF   = sm + OFF_F;
    float* sAdj = sm + OFF_ADJ;
    float* sK0  = sm + OFF_K0;
    float* sK1  = sm + OFF_K1;
    float* sX1  = sm + OFF_X1;

    const uint32_t smb   = smem_u32(sm);
    const uint32_t sAdjB = smb + OFF_ADJ * 4u;
    const uint32_t sK0B  = smb + OFF_K0 * 4u;
    const uint32_t sK1B  = smb + OFF_K1 * 4u;

    const int tid = threadIdx.x;
    const int wid = tid >> 5;
    const int lid = tid & 31;
    const int r4  = lid >> 2;
    const int c4  = lid & 3;
    const int b   = blockIdx.x;

    const int m0 = (wid & 3) * 32;       // M tile base (both GEMMs)
    const int d0 = (wid >> 2) * 32;      // GEMM1 N (=atom) tile base
    const int u0 = (wid >> 2) * 64;      // GEMM2 N (=units) tile base

    const float4* adjB  = reinterpret_cast<const float4*>(adjacency) + (size_t)(b * BOND) * 4096;
    const float4* kerB  = reinterpret_cast<const float4*>(kern)      + (size_t)(b * BOND) * 2048;
    const float4* featB = reinterpret_cast<const float4*>(features)  + (size_t)b * 2048;

    auto stage_adj_chunk = [&](const float4* src, int c) {
        #pragma unroll
        for (int t = 0; t < 4; t++) {
            int i = tid + t * THREADS;          // 0..1023
            int m = i >> 3, j = i & 7;
            cpa16(sAdjB + (uint32_t)(m * P_ADJ + (c * 8 + j) * 4) * 4u,
                  src + m * 32 + c * 8 + j);
        }
    };
    auto stage_K = [&](uint32_t dstB, const float4* src) {
        #pragma unroll
        for (int t = 0; t < 8; t++) {
            int i = tid + t * THREADS;          // 0..2047
            int dd = i >> 5, u4 = i & 31;
            cpa16(dstB + (uint32_t)(dd * P_K + u4 * 4) * 4u, src + i);
        }
    };
    // commit 5 staging groups for bond e1: {C0},{C1},{C2},{C3},{K}
    auto stage_bond = [&](int e1) {
        const float4* adjN = adjB + (size_t)e1 * 4096;
        stage_adj_chunk(adjN, 0); CP_COMMIT();
        stage_adj_chunk(adjN, 1); CP_COMMIT();
        stage_adj_chunk(adjN, 2); CP_COMMIT();
        stage_adj_chunk(adjN, 3); CP_COMMIT();
        stage_K((e1 & 1) ? sK1B : sK0B, kerB + (size_t)e1 * 2048); CP_COMMIT();
    };

    float acc1[2][4][4];
    float acc2[2][8][4];
    #pragma unroll
    for (int mt = 0; mt < 2; mt++) {
        #pragma unroll
        for (int nt = 0; nt < 4; nt++)
            #pragma unroll
            for (int k = 0; k < 4; k++) acc1[mt][nt][k] = 0.0f;
        #pragma unroll
        for (int nt = 0; nt < 8; nt++)
            #pragma unroll
            for (int k = 0; k < 4; k++) acc2[mt][nt][k] = 0.0f;
    }

    // ---- GEMM1 one k-step (8 wide) at chunk c, sub-step ks4; accumulates acc1 ----
    auto g1_step = [&](int c, int ks4) {
        const int k0 = c * 32 + ks4 * 8;
        uint32_t a[2][4], bf[4][2];
        #pragma unroll
        for (int mt = 0; mt < 2; mt++) {
            const float* pa = sAdj + (m0 + mt * 16 + r4) * P_ADJ + k0 + c4;
            a[mt][0] = __float_as_uint(pa[0]);           // raw fp32 (HW tf32 trunc)
            a[mt][1] = __float_as_uint(pa[8 * P_ADJ]);
            a[mt][2] = __float_as_uint(pa[4]);
            a[mt][3] = __float_as_uint(pa[8 * P_ADJ + 4]);
        }
        #pragma unroll
        for (int nt = 0; nt < 4; nt++) {
            const float* pb = sF + (k0 + c4) * P_F + d0 + nt * 8 + r4;
            bf[nt][0] = __float_as_uint(pb[0]);          // pre-rounded at staging
            bf[nt][1] = __float_as_uint(pb[4 * P_F]);
        }
        #pragma unroll
        for (int mt = 0; mt < 2; mt++)
            #pragma unroll
            for (int nt = 0; nt < 4; nt++)
                mma_tf32(acc1[mt][nt], a[mt], bf[nt]);
    };
    // ---- GEMM2 one k-step; accumulates acc2 ----
    auto g2_step = [&](const float* sKe, int ks) {
        const int k0 = ks * 8;
        uint32_t a[2][4], bf[8][2];
        #pragma unroll
        for (int mt = 0; mt < 2; mt++) {
            const float* pa = sX1 + (m0 + mt * 16 + r4) * P_X1 + k0 + c4;
            a[mt][0] = __float_as_uint(pa[0]);           // already tf32-rounded
            a[mt][1] = __float_as_uint(pa[8 * P_X1]);
            a[mt][2] = __float_as_uint(pa[4]);
            a[mt][3] = __float_as_uint(pa[8 * P_X1 + 4]);
        }
        #pragma unroll
        for (int nt = 0; nt < 8; nt++) {
            const float* pb = sKe + (k0 + c4) * P_K + u0 + nt * 8 + r4;
            bf[nt][0] = __float_as_uint(f2tf32f(pb[0]));
            bf[nt][1] = __float_as_uint(f2tf32f(pb[4 * P_K]));
        }
        #pragma unroll
        for (int mt = 0; mt < 2; mt++)
            #pragma unroll
            for (int nt = 0; nt < 8; nt++)
                mma_tf32(acc2[mt][nt], a[mt], bf[nt]);
    };
    // ---- X1 <- acc1 (tf32-rounded), then reset acc1 ----
    auto store_x1 = [&]() {
        #pragma unroll
        for (int mt = 0; mt < 2; mt++) {
            #pragma unroll
            for (int nt = 0; nt < 4; nt++) {
                const int row = m0 + mt * 16 + r4;
                const int col = d0 + nt * 8 + 2 * c4;
                *reinterpret_cast<float2*>(sX1 + row * P_X1 + col) =
                    make_float2(f2tf32f(acc1[mt][nt][0]), f2tf32f(acc1[mt][nt][1]));
                *reinterpret_cast<float2*>(sX1 + (row + 8) * P_X1 + col) =
                    make_float2(f2tf32f(acc1[mt][nt][2]), f2tf32f(acc1[mt][nt][3]));
                #pragma unroll
                for (int k = 0; k < 4; k++) acc1[mt][nt][k] = 0.0f;
            }
        }
    };

    // ---- prologue: F (LDG+cvt+STS), stage bond 0, run G1(0) unfused ----
    {
        #pragma unroll
        for (int t = 0; t < 8; t++) {
            int i = tid + t * THREADS;          // 0..2047
            float4 v = featB[i];
            int node = i >> 4, a4 = i & 15;
            float* d = sF + node * P_F + a4 * 4;
            d[0] = f2tf32f(v.x); d[1] = f2tf32f(v.y);
            d[2] = f2tf32f(v.z); d[3] = f2tf32f(v.w);
        }
        stage_bond(0);
        cp_wait<4>(); __syncthreads();
        g1_step(0, 0); g1_step(0, 1); g1_step(0, 2); g1_step(0, 3);
        cp_wait<3>(); __syncthreads();
        g1_step(1, 0); g1_step(1, 1); g1_step(1, 2); g1_step(1, 3);
        cp_wait<2>(); __syncthreads();
        g1_step(2, 0); g1_step(2, 1); g1_step(2, 2); g1_step(2, 3);
        cp_wait<1>(); __syncthreads();
        g1_step(3, 0); g1_step(3, 1); g1_step(3, 2); g1_step(3, 3);
        cp_wait<0>(); __syncthreads();   // K(0) landed; all adj(0) reads done
        store_x1();                      // X1(0)
        __syncthreads();                 // X1(0) visible
    }

    // ---- fused phases: phase e runs G2(e) interleaved with G1(e+1) ----
    #pragma unroll 1
    for (int e = 0; e < BOND; e++) {
        const float* sKe = (e & 1) ? sK1 : sK0;
        const bool more = (e + 1 < BOND);
        if (more) stage_bond(e + 1);    // overwrites bond-e adj (dead) + other K buf

        if (more) {
            // segment j: wait chunk j of adj(e+1), fuse 4 G1 ks with 2 G2 ks
            cp_wait<4>(); __syncthreads();
            g1_step(0, 0); g2_step(sKe, 0); g1_step(0, 1);
            g1_step(0, 2); g2_step(sKe, 1); g1_step(0, 3);
            cp_wait<3>(); __syncthreads();
            g1_step(1, 0); g2_step(sKe, 2); g1_step(1, 1);
            g1_step(1, 2); g2_step(sKe, 3); g1_step(1, 3);
            cp_wait<2>(); __syncthreads();
            g1_step(2, 0); g2_step(sKe, 4); g1_step(2, 1);
            g1_step(2, 2); g2_step(sKe, 5); g1_step(2, 3);
            cp_wait<1>(); __syncthreads();
            g1_step(3, 0); g2_step(sKe, 6); g1_step(3, 1);
            g1_step(3, 2); g2_step(sKe, 7); g1_step(3, 3);

            cp_wait<0>();        // K(e+1) landed
            __syncthreads();     // barC: all warps' G2(e) X1 reads done; K visible
            store_x1();          // X1(e+1) into the single buffer
            __syncthreads();     // barD: X1(e+1) visible
        } else {
            // last bond: plain G2(4)
            g2_step(sKe, 0); g2_step(sKe, 1); g2_step(sKe, 2); g2_step(sKe, 3);
            g2_step(sKe, 4); g2_step(sKe, 5); g2_step(sKe, 6); g2_step(sKe, 7);
        }
    }

    // ---- epilogue: ReLU + store OUT[b][m][u] ----
    float* ob = out + (size_t)b * (NDIM * UNITS);
    #pragma unroll
    for (int mt = 0; mt < 2; mt++) {
        #pragma unroll
        for (int nt = 0; nt < 8; nt++) {
            const int row = m0 + mt * 16 + r4;
            const int col = u0 + nt * 8 + 2 * c4;
            float2 v0 = make_float2(fmaxf(acc2[mt][nt][0], 0.0f), fmaxf(acc2[mt][nt][1], 0.0f));
            float2 v1 = make_float2(fmaxf(acc2[mt][nt][2], 0.0f), fmaxf(acc2[mt][nt][3], 0.0f));
            *reinterpret_cast<float2*>(ob + row * UNITS + col)       = v0;
            *reinterpret_cast<float2*>(ob + (row + 8) * UNITS + col) = v1;
        }
    }
}

extern "C" void kernel_launch(void* const* d_in, const int* in_sizes, int n_in,
                              void* d_out, int out_size) {
    const float* adj  = nullptr;
    const float* feat = nullptr;
    const float* ker  = nullptr;
    for (int i = 0; i < n_in; i++) {
        if      (in_sizes[i] == BSZ * BOND * NDIM * NDIM)  adj  = (const float*)d_in[i];
        else if (in_sizes[i] == BSZ * NDIM * ATOM)         feat = (const float*)d_in[i];
        else if (in_sizes[i] == BSZ * BOND * ATOM * UNITS) ker  = (const float*)d_in[i];
    }
    if (!adj)  adj  = (const float*)d_in[0];
    if (!feat) feat = (const float*)d_in[1];
    if (!ker)  ker  = (const float*)d_in[2];

    cudaFuncSetAttribute(rgc_kernel, cudaFuncAttributeMaxDynamicSharedMemorySize, SMEM_BYTES);
    rgc_kernel<<<BSZ, THREADS, SMEM_BYTES>>>(adj, feat, ker, (float*)d_out);
}